// round 11
// baseline (speedup 1.0000x reference)
#include <cuda_runtime.h>

// FilterLayer: y[b,c,h,w] = sum_{i,j in 5x5} x_pad[b,c,h+i,w+j] * f[b,i*5+j,h,w]
// B=4, C=3, H=W=512, window=5, zero padding of 2.
// R11: exact R2 structure (best so far, 25.1us) with TH 8->4:
// 128-thread blocks, 8192 blocks, 16 CTAs/SM. Across R2..R10, achieved HBM BW
// correlates with concurrent-CTA count (multi-CTA spread model: front-batched
// LDGs -> ~2x per-CTA completion spread -> DRAM-idle wave tails). Smaller,
// shorter CTAs shrink the absolute spread and smooth the request stream.

#define IMG_H 512
#define IMG_W 512
#define TW 32
#define TH 4
#define NTHREADS (TW * TH)        // 128
#define HALO 2
#define TILE_R (TH + 2 * HALO)    // 8
#define TILE_C (TW + 2 * HALO)    // 36

__global__ __launch_bounds__(NTHREADS)
void filter_layer_kernel(const float* __restrict__ x,
                         const float* __restrict__ f,
                         float* __restrict__ out)
{
    __shared__ float xs[3][TILE_R][TILE_C];

    const int b  = blockIdx.z;
    const int w0 = blockIdx.x * TW;
    const int h0 = blockIdx.y * TH;
    const int tx = threadIdx.x;
    const int ty = threadIdx.y;
    const int tid = ty * TW + tx;

    const int HW = IMG_H * IMG_W;

    // ---- Stage 3-channel x tile with halo (zero-padded at borders) ----
    const float* xb = x + (size_t)b * 3 * HW;
    for (int idx = tid; idx < 3 * TILE_R * TILE_C; idx += NTHREADS) {
        int c   = idx / (TILE_R * TILE_C);
        int rem = idx - c * (TILE_R * TILE_C);
        int r   = rem / TILE_C;
        int col = rem - r * TILE_C;
        int gr  = h0 + r - HALO;
        int gc  = w0 + col - HALO;
        float v = 0.0f;
        if ((unsigned)gr < (unsigned)IMG_H && (unsigned)gc < (unsigned)IMG_W)
            v = __ldg(xb + c * HW + gr * IMG_W + gc);
        xs[c][r][col] = v;
    }
    __syncthreads();

    // ---- Per-pixel 25-tap weighted sum, f value shared across 3 channels ----
    const int h = h0 + ty;
    const int w = w0 + tx;
    const float* fp = f + (size_t)b * 25 * HW + h * IMG_W + w;

    float a0 = 0.0f, a1 = 0.0f, a2 = 0.0f;
    #pragma unroll
    for (int k = 0; k < 25; ++k) {
        const int i = k / 5;
        const int j = k % 5;
        // streaming load: f is touched exactly once -> evict-first policy
        const float fv = __ldcs(fp + (size_t)k * HW);
        a0 = fmaf(xs[0][ty + i][tx + j], fv, a0);
        a1 = fmaf(xs[1][ty + i][tx + j], fv, a1);
        a2 = fmaf(xs[2][ty + i][tx + j], fv, a2);
    }

    float* op = out + (size_t)b * 3 * HW + h * IMG_W + w;
    op[0]              = a0;
    op[(size_t)HW]     = a1;
    op[(size_t)2 * HW] = a2;
}

extern "C" void kernel_launch(void* const* d_in, const int* in_sizes, int n_in,
                              void* d_out, int out_size)
{
    const float* x = (const float*)d_in[0];
    const float* f = (const float*)d_in[1];
    float* out = (float*)d_out;

    dim3 block(TW, TH, 1);                       // 128 threads
    dim3 grid(IMG_W / TW, IMG_H / TH, 4);        // 16 x 128 x 4 = 8192 blocks
    filter_layer_kernel<<<grid, block>>>(x, f, out);
}

// round 13
// speedup vs baseline: 1.0996x; 1.0996x over previous
#include <cuda_runtime.h>

// FilterLayer: y[b,c,h,w] = sum_{i,j in 5x5} x_pad[b,c,h+i,w+j] * f[b,i*5+j,h,w]
// B=4, C=3, H=W=512, window=5, zero padding of 2.
// R12: single-wave PERSISTENT kernel. R2's per-tile work (best: 25.1us) had
// DRAM idle 43%: 3.46 launch waves -> ragged tail (~29% of time at half
// demand) + per-wave completion spread from 25-wide front-batched LDGs.
// Here: exactly one wave (148 SMs x 8 blocks = 1184 blocks), each block
// grid-strides over 3-4 of the 4096 tiles. No wave transitions, ±1-tile
// imbalance. Per-tile work identical to R2.

#define IMG_H 512
#define IMG_W 512
#define TW 32
#define TH 8
#define HALO 2
#define TILE_R (TH + 2 * HALO)   // 12
#define TILE_C (TW + 2 * HALO)   // 36
#define NTILES_X (IMG_W / TW)    // 16
#define NTILES_Y (IMG_H / TH)    // 64
#define NTILES   (NTILES_X * NTILES_Y * 4)   // 4096
#define NBLOCKS  (148 * 8)       // one full wave at 8 blocks/SM

__global__ __launch_bounds__(256, 8)
void filter_layer_kernel(const float* __restrict__ x,
                         const float* __restrict__ f,
                         float* __restrict__ out)
{
    __shared__ float xs[3][TILE_R][TILE_C];

    const int tx = threadIdx.x;
    const int ty = threadIdx.y;
    const int tid = ty * TW + tx;
    const int HW = IMG_H * IMG_W;

    for (int t = blockIdx.x; t < NTILES; t += NBLOCKS) {
        // decode tile: b = t / 1024, hy = (t % 1024) / 16, wx = t % 16
        const int b   = t >> 10;
        const int rem = t & 1023;
        const int h0  = (rem >> 4) * TH;
        const int w0  = (rem & 15) * TW;

        // ---- Stage 3-channel x tile with halo (zero-padded at borders) ----
        const float* xb = x + (size_t)b * 3 * HW;
        for (int idx = tid; idx < 3 * TILE_R * TILE_C; idx += 256) {
            int c   = idx / (TILE_R * TILE_C);
            int r2  = idx - c * (TILE_R * TILE_C);
            int r   = r2 / TILE_C;
            int col = r2 - r * TILE_C;
            int gr  = h0 + r - HALO;
            int gc  = w0 + col - HALO;
            float v = 0.0f;
            if ((unsigned)gr < (unsigned)IMG_H && (unsigned)gc < (unsigned)IMG_W)
                v = __ldg(xb + c * HW + gr * IMG_W + gc);
            xs[c][r][col] = v;
        }
        __syncthreads();

        // ---- Per-pixel 25-tap weighted sum, f shared across 3 channels ----
        const int h = h0 + ty;
        const int w = w0 + tx;
        const float* fp = f + (size_t)b * 25 * HW + h * IMG_W + w;

        float a0 = 0.0f, a1 = 0.0f, a2 = 0.0f;
        #pragma unroll
        for (int k = 0; k < 25; ++k) {
            const int i = k / 5;
            const int j = k % 5;
            const float fv = fp[(size_t)k * HW];
            a0 = fmaf(xs[0][ty + i][tx + j], fv, a0);
            a1 = fmaf(xs[1][ty + i][tx + j], fv, a1);
            a2 = fmaf(xs[2][ty + i][tx + j], fv, a2);
        }

        float* op = out + (size_t)b * 3 * HW + h * IMG_W + w;
        op[0]              = a0;
        op[(size_t)HW]     = a1;
        op[(size_t)2 * HW] = a2;

        // protect xs before next iteration's restaging
        __syncthreads();
    }
}

extern "C" void kernel_launch(void* const* d_in, const int* in_sizes, int n_in,
                              void* d_out, int out_size)
{
    const float* x = (const float*)d_in[0];
    const float* f = (const float*)d_in[1];
    float* out = (float*)d_out;

    dim3 block(TW, TH, 1);            // 256 threads
    dim3 grid(NBLOCKS, 1, 1);         // exactly one wave: 1184 blocks
    filter_layer_kernel<<<grid, block>>>(x, f, out);
}

// round 14
// speedup vs baseline: 1.2574x; 1.1436x over previous
#include <cuda_runtime.h>

// FilterLayer: y[b,c,h,w] = sum_{i,j in 5x5} x_pad[b,c,h+i,w+j] * f[b,i*5+j,h,w]
// B=4, C=3, H=W=512, window=5, zero padding of 2.
// R13: R2 (best, 25.1us) with smem padded to ~30KB so exactly 7 CTAs/SM fit.
// With 8 CTAs/SM each SM pipe runs 3.46 tiles -> quantizes to 4 => ~13% drain
// idle per replay. At 7 CTAs/SM: 27.7 tiles/SM over 7 pipes = 3.95 -> 4,
// ~1% loss. Warp count unchanged (56 vs 55), so achieved BW side is untouched.
// Padding lives in the row stride; LDS stays lane-consecutive conflict-free.

#define IMG_H 512
#define IMG_W 512
#define TW 32
#define TH 8
#define HALO 2
#define TILE_R (TH + 2 * HALO)   // 12
#define TILE_C (TW + 2 * HALO)   // 36
#define PAD_C  213               // 3*12*213*4 = 30672B -> 7 CTAs/SM (not 8)

__global__ __launch_bounds__(256)
void filter_layer_kernel(const float* __restrict__ x,
                         const float* __restrict__ f,
                         float* __restrict__ out)
{
    __shared__ float xs[3][TILE_R][PAD_C];

    const int b  = blockIdx.z;
    const int w0 = blockIdx.x * TW;
    const int h0 = blockIdx.y * TH;
    const int tx = threadIdx.x;
    const int ty = threadIdx.y;
    const int tid = ty * TW + tx;

    const int HW = IMG_H * IMG_W;

    // ---- Stage 3-channel x tile with halo (zero-padded at borders) ----
    const float* xb = x + (size_t)b * 3 * HW;
    for (int idx = tid; idx < 3 * TILE_R * TILE_C; idx += 256) {
        int c   = idx / (TILE_R * TILE_C);
        int rem = idx - c * (TILE_R * TILE_C);
        int r   = rem / TILE_C;
        int col = rem - r * TILE_C;
        int gr  = h0 + r - HALO;
        int gc  = w0 + col - HALO;
        float v = 0.0f;
        if ((unsigned)gr < (unsigned)IMG_H && (unsigned)gc < (unsigned)IMG_W)
            v = __ldg(xb + c * HW + gr * IMG_W + gc);
        xs[c][r][col] = v;
    }
    __syncthreads();

    // ---- Per-pixel 25-tap weighted sum, f value shared across 3 channels ----
    const int h = h0 + ty;
    const int w = w0 + tx;
    const float* fp = f + (size_t)b * 25 * HW + h * IMG_W + w;

    float a0 = 0.0f, a1 = 0.0f, a2 = 0.0f;
    #pragma unroll
    for (int k = 0; k < 25; ++k) {
        const int i = k / 5;
        const int j = k % 5;
        // streaming load: f is touched exactly once -> evict-first policy
        const float fv = __ldcs(fp + (size_t)k * HW);
        a0 = fmaf(xs[0][ty + i][tx + j], fv, a0);
        a1 = fmaf(xs[1][ty + i][tx + j], fv, a1);
        a2 = fmaf(xs[2][ty + i][tx + j], fv, a2);
    }

    float* op = out + (size_t)b * 3 * HW + h * IMG_W + w;
    op[0]              = a0;
    op[(size_t)HW]     = a1;
    op[(size_t)2 * HW] = a2;
}

extern "C" void kernel_launch(void* const* d_in, const int* in_sizes, int n_in,
                              void* d_out, int out_size)
{
    const float* x = (const float*)d_in[0];
    const float* f = (const float*)d_in[1];
    float* out = (float*)d_out;

    dim3 block(TW, TH, 1);                       // 256 threads
    dim3 grid(IMG_W / TW, IMG_H / TH, 4);        // 16 x 64 x 4 = 4096 blocks
    filter_layer_kernel<<<grid, block>>>(x, f, out);
}